// round 6
// baseline (speedup 1.0000x reference)
#include <cuda_runtime.h>
#include <cuda_fp16.h>
#include <cstdint>

#define A_DIM 1024
#define B_DIM 16
#define DMODEL 512
#define NHEAD 8
#define HEAD_DIM 64
#define NTOK (A_DIM * B_DIM)   // 16384

// Scratch (allocation-free)
__device__ __half g_qhi[NTOK * DMODEL];
__device__ __half g_qlo[NTOK * DMODEL];
__device__ __half g_khi[NTOK * DMODEL];
__device__ __half g_vhi[NTOK * DMODEL];
__device__ float  g_attn[NTOK * DMODEL];

__device__ __forceinline__ uint32_t f2tf32(float f) {
    uint32_t r;
    asm("cvt.rna.tf32.f32 %0, %1;" : "=r"(r) : "f"(f));
    return r;
}

__device__ __forceinline__ void mma_tf32(float* c, const uint32_t* a,
                                         uint32_t b0, uint32_t b1) {
    asm volatile(
        "mma.sync.aligned.m16n8k8.row.col.f32.tf32.tf32.f32 "
        "{%0,%1,%2,%3}, {%4,%5,%6,%7}, {%8,%9}, {%0,%1,%2,%3};"
        : "+f"(c[0]), "+f"(c[1]), "+f"(c[2]), "+f"(c[3])
        : "r"(a[0]), "r"(a[1]), "r"(a[2]), "r"(a[3]), "r"(b0), "r"(b1));
}

__device__ __forceinline__ void mma_f16(float* c, const uint32_t* a,
                                        uint32_t b0, uint32_t b1) {
    asm volatile(
        "mma.sync.aligned.m16n8k16.row.col.f32.f16.f16.f32 "
        "{%0,%1,%2,%3}, {%4,%5,%6,%7}, {%8,%9}, {%0,%1,%2,%3};"
        : "+f"(c[0]), "+f"(c[1]), "+f"(c[2]), "+f"(c[3])
        : "r"(a[0]), "r"(a[1]), "r"(a[2]), "r"(a[3]), "r"(b0), "r"(b1));
}

__device__ __forceinline__ uint32_t pack_h2(float x, float y) {
    __half2 h = __floats2half2_rn(x, y);
    return *(uint32_t*)&h;
}

__device__ __forceinline__ void split_h2(float x, float y,
                                         uint32_t& hi, uint32_t& lo) {
    __half2 h = __floats2half2_rn(x, y);
    float rx = x - __half2float(__low2half(h));
    float ry = y - __half2float(__high2half(h));
    __half2 l = __floats2half2_rn(rx, ry);
    hi = *(uint32_t*)&h;
    lo = *(uint32_t*)&l;
}

__device__ __forceinline__ void cp16(uint32_t dst_s, const void* src) {
    asm volatile("cp.async.cg.shared.global [%0], [%1], 16;"
                 :: "r"(dst_s), "l"(src));
}

// ---------------------------------------------------------------------------
// GEMM mainloop (cp.async 2-stage, raw fp32, in-register tf32 cvt).
// BM=128, BN=128, BK=32; 8 warps, warp tile 64x32; dyn smem 64 KB.
// Fills acc[4][4][4] for warp tile at (m0+wm0, n0+wn0).
// ---------------------------------------------------------------------------
__device__ __forceinline__ void gemm_body(
    const float* __restrict__ X, const float* __restrict__ W,
    uint32_t* smp, float acc[4][4][4],
    int m0, int n0, int wm0, int wn0, int gid, int tig)
{
    const int tid = threadIdx.x;
    const int lr  = tid >> 3;
    const int lc4 = (tid & 7) * 4;
    const uint32_t smem_base = (uint32_t)__cvta_generic_to_shared(smp);

    auto issue = [&](int k0, int buf) {
        uint32_t xb = smem_base + (uint32_t)buf * 8192u * 4u;
        uint32_t wb = xb + 4096u * 4u;
#pragma unroll
        for (int it = 0; it < 4; it++) {
            int rr = lr + it * 32;
            uint32_t cb = (uint32_t)lc4 ^ ((rr & 7) << 2);
            cp16(xb + (rr * 32 + cb) * 4, &X[(size_t)(m0 + rr) * 512 + k0 + lc4]);
            cp16(wb + (rr * 32 + cb) * 4, &W[(size_t)(n0 + rr) * 512 + k0 + lc4]);
        }
        asm volatile("cp.async.commit_group;" ::: "memory");
    };

    issue(0, 0);
    issue(32, 1);

    for (int i = 0; i < 16; i++) {
        if (i < 15) { asm volatile("cp.async.wait_group 1;" ::: "memory"); }
        else        { asm volatile("cp.async.wait_group 0;" ::: "memory"); }
        __syncthreads();

        const uint32_t* Xs = smp + (i & 1) * 8192;
        const uint32_t* Ws = Xs + 4096;

#pragma unroll
        for (int kk = 0; kk < 32; kk += 8) {
            uint32_t af[4][4], bf[4][2];
#pragma unroll
            for (int mt = 0; mt < 4; mt++) {
                int ra = wm0 + mt * 16 + gid;
                uint32_t sw = (ra & 7) << 2;
                uint32_t c0 = (uint32_t)(kk + tig) ^ sw;
                uint32_t c1 = (uint32_t)(kk + tig + 4) ^ sw;
                af[mt][0] = f2tf32(__uint_as_float(Xs[ra * 32 + c0]));
                af[mt][1] = f2tf32(__uint_as_float(Xs[(ra + 8) * 32 + c0]));
                af[mt][2] = f2tf32(__uint_as_float(Xs[ra * 32 + c1]));
                af[mt][3] = f2tf32(__uint_as_float(Xs[(ra + 8) * 32 + c1]));
            }
#pragma unroll
            for (int nt = 0; nt < 4; nt++) {
                int rb = wn0 + nt * 8 + gid;
                uint32_t sw = (rb & 7) << 2;
                bf[nt][0] = f2tf32(__uint_as_float(Ws[rb * 32 + ((uint32_t)(kk + tig) ^ sw)]));
                bf[nt][1] = f2tf32(__uint_as_float(Ws[rb * 32 + ((uint32_t)(kk + tig + 4) ^ sw)]));
            }
#pragma unroll
            for (int mt = 0; mt < 4; mt++)
#pragma unroll
                for (int nt = 0; nt < 4; nt++)
                    mma_tf32(acc[mt][nt], af[mt], bf[nt][0], bf[nt][1]);
        }
        __syncthreads();
        if (i < 14) issue((i + 2) * 32, i & 1);
    }
}

// ---------------------------------------------------------------------------
// QKV projection: z=0 -> Q (hi/lo split halves, [pair][a][d]),
//                 z=1 -> K (hi halves, [pair][a][d]),
//                 z=2 -> V (hi halves, kv-pair packed [pair][a/2][d][2]).
// ---------------------------------------------------------------------------
__global__ __launch_bounds__(256, 2) void gemm_qkv(
    const float* __restrict__ X,
    const float* __restrict__ W0, const float* __restrict__ W1,
    const float* __restrict__ W2,
    const float* __restrict__ b0p, const float* __restrict__ b1p,
    const float* __restrict__ b2p)
{
    extern __shared__ uint32_t smp[];
    const int z = blockIdx.z;
    const float* W    = z == 0 ? W0  : z == 1 ? W1  : W2;
    const float* bias = z == 0 ? b0p : z == 1 ? b1p : b2p;

    const int tid  = threadIdx.x;
    const int warp = tid >> 5;
    const int lane = tid & 31;
    const int gid  = lane >> 2;
    const int tig  = lane & 3;
    const int m0 = blockIdx.x * 128;
    const int n0 = blockIdx.y * 128;
    const int wm0 = (warp & 1) * 64;
    const int wn0 = (warp >> 1) * 32;

    float acc[4][4][4];
#pragma unroll
    for (int mt = 0; mt < 4; mt++)
#pragma unroll
        for (int nt = 0; nt < 4; nt++)
#pragma unroll
            for (int i = 0; i < 4; i++) acc[mt][nt][i] = 0.0f;

    gemm_body(X, W, smp, acc, m0, n0, wm0, wn0, gid, tig);

    uint32_t* qhi_w = (uint32_t*)g_qhi;
    uint32_t* qlo_w = (uint32_t*)g_qlo;
    uint32_t* khi_w = (uint32_t*)g_khi;

#pragma unroll
    for (int mt = 0; mt < 4; mt++) {
        int mr = m0 + wm0 + mt * 16 + gid;
#pragma unroll
        for (int nt = 0; nt < 4; nt++) {
            int nc = n0 + wn0 + nt * 8 + tig * 2;
            float2 b2 = *(const float2*)&bias[nc];
            float v0 = acc[mt][nt][0] + b2.x, v1 = acc[mt][nt][1] + b2.y;
            float v2 = acc[mt][nt][2] + b2.x, v3 = acc[mt][nt][3] + b2.y;
            int h = nc >> 6, d = nc & 63;
            int a0 = mr >> 4;                 // same a for mr and mr+8
            int p0 = (mr & 15) * 8 + h;
            int p1 = ((mr + 8) & 15) * 8 + h;
            size_t w0 = ((size_t)p0 * 1024 + a0) * 32 + (d >> 1);
            size_t w1 = ((size_t)p1 * 1024 + a0) * 32 + (d >> 1);
            if (z == 0) {
                uint32_t hi, lo;
                split_h2(v0, v1, hi, lo);
                qhi_w[w0] = hi; qlo_w[w0] = lo;
                split_h2(v2, v3, hi, lo);
                qhi_w[w1] = hi; qlo_w[w1] = lo;
            } else if (z == 1) {
                khi_w[w0] = pack_h2(v0, v1);
                khi_w[w1] = pack_h2(v2, v3);
            } else {
                int a2 = a0 >> 1, par = a0 & 1;
                size_t h0 = (((size_t)p0 * 512 + a2) * 64 + d) * 2 + par;
                size_t h1 = (((size_t)p1 * 512 + a2) * 64 + d) * 2 + par;
                g_vhi[h0]     = __float2half_rn(v0);
                g_vhi[h0 + 2] = __float2half_rn(v1);
                g_vhi[h1]     = __float2half_rn(v2);
                g_vhi[h1 + 2] = __float2half_rn(v3);
            }
        }
    }
}

// ---------------------------------------------------------------------------
// Output projection: plain fp32 out + bias.
// ---------------------------------------------------------------------------
__global__ __launch_bounds__(256, 2) void gemm_out(
    const float* __restrict__ X, const float* __restrict__ W,
    const float* __restrict__ bias, float* __restrict__ Y)
{
    extern __shared__ uint32_t smp[];
    const int tid  = threadIdx.x;
    const int warp = tid >> 5;
    const int lane = tid & 31;
    const int gid  = lane >> 2;
    const int tig  = lane & 3;
    const int m0 = blockIdx.x * 128;
    const int n0 = blockIdx.y * 128;
    const int wm0 = (warp & 1) * 64;
    const int wn0 = (warp >> 1) * 32;

    float acc[4][4][4];
#pragma unroll
    for (int mt = 0; mt < 4; mt++)
#pragma unroll
        for (int nt = 0; nt < 4; nt++)
#pragma unroll
            for (int i = 0; i < 4; i++) acc[mt][nt][i] = 0.0f;

    gemm_body(X, W, smp, acc, m0, n0, wm0, wn0, gid, tig);

#pragma unroll
    for (int mt = 0; mt < 4; mt++) {
        int mr = m0 + wm0 + mt * 16 + gid;
#pragma unroll
        for (int nt = 0; nt < 4; nt++) {
            int nc = n0 + wn0 + nt * 8 + tig * 2;
            float2 b2 = *(const float2*)&bias[nc];
            float2 r0 = { acc[mt][nt][0] + b2.x, acc[mt][nt][1] + b2.y };
            *(float2*)&Y[(size_t)mr * 512 + nc] = r0;
            float2 r1 = { acc[mt][nt][2] + b2.x, acc[mt][nt][3] + b2.y };
            *(float2*)&Y[(size_t)(mr + 8) * 512 + nc] = r1;
        }
    }
}

// ---------------------------------------------------------------------------
// fp16 2-term flash attention with cp.async double-buffered K/V.
// K/V arrive pre-converted to half in attention-native layouts.
// grid = (A/128, 128 pairs), 8 warps x 16 q-rows, 2 CTAs/SM.
// ---------------------------------------------------------------------------
#define KP 36
#define VP 72
#define STG_W 4608      // words per stage (K 64*36 + V 32*72)

__global__ __launch_bounds__(256, 2) void attn_mma(
    const float* __restrict__ rbias,
    float* __restrict__ O)
{
    __shared__ uint32_t sm_kv[2 * STG_W];

    const int tid  = threadIdx.x;
    const int warp = tid >> 5;
    const int lane = tid & 31;
    const int gid  = lane >> 2;
    const int tig  = lane & 3;

    const int pair = blockIdx.y;
    const int b = pair >> 3;
    const int h = pair & 7;
    const int q0 = blockIdx.x * 128;
    const int wm = warp * 16;
    const float scale = 0.125f;

    const uint32_t smem_base = (uint32_t)__cvta_generic_to_shared(sm_kv);
    const char* kg_base = (const char*)(g_khi + (size_t)pair * 1024 * 64);
    const char* vg_base = (const char*)(g_vhi + (size_t)pair * 512 * 128);

    auto issue_kv = [&](int kb, int buf) {
        uint32_t sbase = smem_base + (uint32_t)buf * STG_W * 4u;
        uint32_t vsb   = sbase + 64u * KP * 4u;
        const char* kg = kg_base + (size_t)kb * 128;
        const char* vg = vg_base + (size_t)kb * 128;   // kb/2 rows * 256B
#pragma unroll
        for (int it = 0; it < 2; it++) {
            int c = tid + it * 256;
            int r = c >> 3, ch = c & 7;
            cp16(sbase + r * (KP * 4) + ch * 16, kg + r * 128 + ch * 16);
            int r2 = c >> 4, c2 = c & 15;
            cp16(vsb + r2 * (VP * 4) + c2 * 16, vg + r2 * 256 + c2 * 16);
        }
        asm volatile("cp.async.commit_group;" ::: "memory");
    };

    issue_kv(0, 0);
    issue_kv(64, 1);

    // Q fragments from pre-split buffers
    uint32_t qhi[4][4], qlo[4][4];
    {
        const uint32_t* qh = (const uint32_t*)g_qhi;
        const uint32_t* ql = (const uint32_t*)g_qlo;
        size_t base0 = ((size_t)pair * 1024 + q0 + wm + gid) * 32;
        size_t base1 = base0 + 8 * 32;
#pragma unroll
        for (int kt = 0; kt < 4; kt++) {
            size_t c0 = kt * 8 + tig;
            qhi[kt][0] = qh[base0 + c0];     qlo[kt][0] = ql[base0 + c0];
            qhi[kt][1] = qh[base1 + c0];     qlo[kt][1] = ql[base1 + c0];
            qhi[kt][2] = qh[base0 + c0 + 4]; qlo[kt][2] = ql[base0 + c0 + 4];
            qhi[kt][3] = qh[base1 + c0 + 4]; qlo[kt][3] = ql[base1 + c0 + 4];
        }
    }

    float o[8][4];
#pragma unroll
    for (int nt = 0; nt < 8; nt++)
#pragma unroll
        for (int i = 0; i < 4; i++) o[nt][i] = 0.0f;
    float m0r = -1e30f, m1r = -1e30f, l0r = 0.0f, l1r = 0.0f;

    for (int i = 0; i < 16; i++) {
        if (i < 15) { asm volatile("cp.async.wait_group 1;" ::: "memory"); }
        else        { asm volatile("cp.async.wait_group 0;" ::: "memory"); }
        __syncthreads();

        const uint32_t* Khi = sm_kv + (i & 1) * STG_W;
        const uint32_t* Vph = Khi + 64 * KP;
        const int kb = i * 64;

        // ---- S = Q K^T ----
        float s[8][4];
#pragma unroll
        for (int nt = 0; nt < 8; nt++)
#pragma unroll
            for (int ii = 0; ii < 4; ii++) s[nt][ii] = 0.0f;

#pragma unroll
        for (int kt = 0; kt < 4; kt++) {
#pragma unroll
            for (int nt = 0; nt < 8; nt++) {
                int wb = (nt * 8 + gid) * KP + kt * 8 + tig;
                uint32_t bh0 = Khi[wb], bh1 = Khi[wb + 4];
                mma_f16(s[nt], qhi[kt], bh0, bh1);
                mma_f16(s[nt], qlo[kt], bh0, bh1);
            }
        }

        // ---- scale + relation bias ----
        {
            const float* br0 = &rbias[(size_t)(q0 + wm + gid) * A_DIM + kb];
            const float* br1 = br0 + 8 * A_DIM;
#pragma unroll
            for (int nt = 0; nt < 8; nt++) {
                float2 b0 = *(const float2*)&br0[nt * 8 + 2 * tig];
                float2 b1 = *(const float2*)&br1[nt * 8 + 2 * tig];
                s[nt][0] = s[nt][0] * scale + b0.x;
                s[nt][1] = s[nt][1] * scale + b0.y;
                s[nt][2] = s[nt][2] * scale + b1.x;
                s[nt][3] = s[nt][3] * scale + b1.y;
            }
        }

        // ---- online softmax ----
        {
            float mx0 = -1e30f, mx1 = -1e30f;
#pragma unroll
            for (int nt = 0; nt < 8; nt++) {
                mx0 = fmaxf(mx0, fmaxf(s[nt][0], s[nt][1]));
                mx1 = fmaxf(mx1, fmaxf(s[nt][2], s[nt][3]));
            }
            mx0 = fmaxf(mx0, __shfl_xor_sync(0xffffffffu, mx0, 1));
            mx0 = fmaxf(mx0, __shfl_xor_sync(0xffffffffu, mx0, 2));
            mx1 = fmaxf(mx1, __shfl_xor_sync(0xffffffffu, mx1, 1));
            mx1 = fmaxf(mx1, __shfl_xor_sync(0xffffffffu, mx1, 2));

            float mn0 = fmaxf(m0r, mx0);
            float mn1 = fmaxf(m1r, mx1);
            float c0 = __expf(m0r - mn0);
            float c1 = __expf(m1r - mn1);
            m0r = mn0; m1r = mn1;

            float rs0 = 0.0f, rs1 = 0.0f;
#pragma unroll
            for (int nt = 0; nt < 8; nt++) {
                s[nt][0] = __expf(s[nt][0] - mn0);
                s[nt][1] = __expf(s[nt][1] - mn0);
                s[nt][2] = __expf(s[nt][2] - mn1);
                s[nt][3] = __expf(s[nt][3] - mn1);
                rs0 += s[nt][0] + s[nt][1];
                rs1 += s[nt][2] + s[nt][3];
            }
            rs0 += __shfl_xor_sync(0xffffffffu, rs0, 1);
            rs0 += __shfl_xor_sync(0xffffffffu, rs0, 2);
            rs1 += __shfl_xor_sync(0xffffffffu, rs1, 1);
            rs1 += __shfl_xor_sync(0xffffffffu, rs1, 2);

            l0r = l0r * c0 + rs0;
            l1r = l1r * c1 + rs1;
#pragma unroll
            for (int nt = 0; nt < 8; nt++) {
                o[nt][0] *= c0; o[nt][1] *= c0;
                o[nt][2] *= c1; o[nt][3] *= c1;
            }
        }

        // ---- O += P V (P hi+lo from registers, V hi only) ----
#pragma unroll
        for (int j = 0; j < 4; j++) {
            uint32_t ah[4], al[4];
            split_h2(s[2*j][0],   s[2*j][1],   ah[0], al[0]);
            split_h2(s[2*j][2],   s[2*j][3],   ah[1], al[1]);
            split_h2(s[2*j+1][0], s[2*j+1][1], ah[2], al[2]);
            split_h2(s[2*j+1][2], s[2*j+1][3], ah[3], al[3]);
#pragma unroll
            for (int nt = 0; nt < 8; nt++) {
                int wb = (j * 8 + tig) * VP + nt * 8 + gid;
                uint32_t bh0 = Vph[wb], bh1 = Vph[wb + 4 * VP];
                mma_f16(o[nt], ah, bh0, bh1);
                mma_f16(o[nt], al, bh0, bh1);
            }
        }
        __syncthreads();
        if (i < 14) issue_kv((i + 2) * 64, i & 1);
    }

    // ---- normalize + write (token-major fp32 for output GEMM) ----
    {
        float i0 = 1.0f / l0r, i1 = 1.0f / l1r;
        const int r0g = q0 + wm + gid;
        size_t base0 = (size_t)(r0g * B_DIM + b) * DMODEL + h * HEAD_DIM;
        size_t base1 = base0 + (size_t)8 * B_DIM * DMODEL;
#pragma unroll
        for (int nt = 0; nt < 8; nt++) {
            int c = nt * 8 + 2 * tig;
            float2 r0 = { o[nt][0] * i0, o[nt][1] * i0 };
            float2 r1 = { o[nt][2] * i1, o[nt][3] * i1 };
            *(float2*)&O[base0 + c] = r0;
            *(float2*)&O[base1 + c] = r1;
        }
    }
}

// ---------------------------------------------------------------------------

extern "C" void kernel_launch(void* const* d_in, const int* in_sizes, int n_in,
                              void* d_out, int out_size)
{
    const float* src   = (const float*)d_in[0];
    const float* rbias = (const float*)d_in[1];
    const float* Wq    = (const float*)d_in[2];
    const float* bq    = (const float*)d_in[3];
    const float* Wk    = (const float*)d_in[4];
    const float* bk    = (const float*)d_in[5];
    const float* Wv    = (const float*)d_in[6];
    const float* bv    = (const float*)d_in[7];
    const float* Wo    = (const float*)d_in[8];
    const float* bo    = (const float*)d_in[9];
    float* out = (float*)d_out;

    float* ga;
    cudaGetSymbolAddress((void**)&ga, g_attn);

    cudaFuncSetAttribute(gemm_qkv, cudaFuncAttributeMaxDynamicSharedMemorySize, 65536);
    cudaFuncSetAttribute(gemm_out, cudaFuncAttributeMaxDynamicSharedMemorySize, 65536);

    // 1) fused QKV projection (writes attention-native half formats)
    gemm_qkv<<<dim3(128, 4, 3), 256, 65536>>>(src, Wq, Wk, Wv, bq, bk, bv);

    // 2) attention
    attn_mma<<<dim3(A_DIM / 128, B_DIM * NHEAD), 256>>>(rbias, ga);

    // 3) output projection
    gemm_out<<<dim3(128, 4, 1), 256, 65536>>>(ga, Wo, bo, out);
}

// round 7
// speedup vs baseline: 1.0477x; 1.0477x over previous
#include <cuda_runtime.h>
#include <cuda_fp16.h>
#include <cstdint>

#define A_DIM 1024
#define B_DIM 16
#define DMODEL 512
#define NHEAD 8
#define HEAD_DIM 64
#define NTOK (A_DIM * B_DIM)   // 16384

// Scratch (allocation-free)
__device__ __half g_qhi[NTOK * DMODEL];
__device__ __half g_qlo[NTOK * DMODEL];
__device__ __half g_khi[NTOK * DMODEL];
__device__ __half g_vhi[NTOK * DMODEL];
__device__ float  g_attn[NTOK * DMODEL];
__device__ float  g_x32[NTOK * DMODEL];
__device__ float  g_wq32[DMODEL * DMODEL];
__device__ float  g_wk32[DMODEL * DMODEL];
__device__ float  g_wv32[DMODEL * DMODEL];
__device__ float  g_wo32[DMODEL * DMODEL];

__device__ __forceinline__ uint32_t f2tf32(float f) {
    uint32_t r;
    asm("cvt.rna.tf32.f32 %0, %1;" : "=r"(r) : "f"(f));
    return r;
}

__device__ __forceinline__ void mma_tf32(float* c, const uint32_t* a,
                                         uint32_t b0, uint32_t b1) {
    asm volatile(
        "mma.sync.aligned.m16n8k8.row.col.f32.tf32.tf32.f32 "
        "{%0,%1,%2,%3}, {%4,%5,%6,%7}, {%8,%9}, {%0,%1,%2,%3};"
        : "+f"(c[0]), "+f"(c[1]), "+f"(c[2]), "+f"(c[3])
        : "r"(a[0]), "r"(a[1]), "r"(a[2]), "r"(a[3]), "r"(b0), "r"(b1));
}

__device__ __forceinline__ void mma_f16(float* c, const uint32_t* a,
                                        uint32_t b0, uint32_t b1) {
    asm volatile(
        "mma.sync.aligned.m16n8k16.row.col.f32.f16.f16.f32 "
        "{%0,%1,%2,%3}, {%4,%5,%6,%7}, {%8,%9}, {%0,%1,%2,%3};"
        : "+f"(c[0]), "+f"(c[1]), "+f"(c[2]), "+f"(c[3])
        : "r"(a[0]), "r"(a[1]), "r"(a[2]), "r"(a[3]), "r"(b0), "r"(b1));
}

__device__ __forceinline__ uint32_t pack_h2(float x, float y) {
    __half2 h = __floats2half2_rn(x, y);
    return *(uint32_t*)&h;
}

__device__ __forceinline__ void split_h2(float x, float y,
                                         uint32_t& hi, uint32_t& lo) {
    __half2 h = __floats2half2_rn(x, y);
    float rx = x - __half2float(__low2half(h));
    float ry = y - __half2float(__high2half(h));
    __half2 l = __floats2half2_rn(rx, ry);
    hi = *(uint32_t*)&h;
    lo = *(uint32_t*)&l;
}

__device__ __forceinline__ void cp16(uint32_t dst_s, const void* src) {
    asm volatile("cp.async.cg.shared.global [%0], [%1], 16;"
                 :: "r"(dst_s), "l"(src));
}

// ---------------------------------------------------------------------------
// Pre-round src + weights to tf32 (rna) so GEMM mainloops carry no CVTs.
// ---------------------------------------------------------------------------
#define NX4 2097152   // NTOK*DMODEL/4
#define NW4 65536     // DMODEL*DMODEL/4

__global__ void tf32_round_all(
    const float4* __restrict__ src,
    const float4* __restrict__ wq, const float4* __restrict__ wk,
    const float4* __restrict__ wv, const float4* __restrict__ wo,
    float4* __restrict__ xo,
    float4* __restrict__ wqo, float4* __restrict__ wko,
    float4* __restrict__ wvo, float4* __restrict__ woo)
{
    int idx = blockIdx.x * 256 + threadIdx.x;
    if (idx >= NX4 + 4 * NW4) return;
    const float4* in; float4* out; int off;
    if (idx < NX4) { in = src; out = xo; off = idx; }
    else {
        int t = idx - NX4;
        int seg = t >> 16;
        off = t & (NW4 - 1);
        in  = seg == 0 ? wq  : seg == 1 ? wk  : seg == 2 ? wv  : wo;
        out = seg == 0 ? wqo : seg == 1 ? wko : seg == 2 ? wvo : woo;
    }
    float4 v = in[off];
    v.x = __uint_as_float(f2tf32(v.x));
    v.y = __uint_as_float(f2tf32(v.y));
    v.z = __uint_as_float(f2tf32(v.z));
    v.w = __uint_as_float(f2tf32(v.w));
    out[off] = v;
}

// ---------------------------------------------------------------------------
// GEMM mainloop (cp.async 2-stage, inputs pre-rounded to tf32, no CVTs).
// BM=128, BN=128, BK=32; 8 warps, warp tile 64x32; dyn smem 64 KB.
// ---------------------------------------------------------------------------
__device__ __forceinline__ void gemm_body(
    const float* __restrict__ X, const float* __restrict__ W,
    uint32_t* smp, float acc[4][4][4],
    int m0, int n0, int wm0, int wn0, int gid, int tig)
{
    const int tid = threadIdx.x;
    const int lr  = tid >> 3;
    const int lc4 = (tid & 7) * 4;
    const uint32_t smem_base = (uint32_t)__cvta_generic_to_shared(smp);

    auto issue = [&](int k0, int buf) {
        uint32_t xb = smem_base + (uint32_t)buf * 8192u * 4u;
        uint32_t wb = xb + 4096u * 4u;
#pragma unroll
        for (int it = 0; it < 4; it++) {
            int rr = lr + it * 32;
            uint32_t cb = (uint32_t)lc4 ^ ((rr & 7) << 2);
            cp16(xb + (rr * 32 + cb) * 4, &X[(size_t)(m0 + rr) * 512 + k0 + lc4]);
            cp16(wb + (rr * 32 + cb) * 4, &W[(size_t)(n0 + rr) * 512 + k0 + lc4]);
        }
        asm volatile("cp.async.commit_group;" ::: "memory");
    };

    issue(0, 0);
    issue(32, 1);

    for (int i = 0; i < 16; i++) {
        if (i < 15) { asm volatile("cp.async.wait_group 1;" ::: "memory"); }
        else        { asm volatile("cp.async.wait_group 0;" ::: "memory"); }
        __syncthreads();

        const uint32_t* Xs = smp + (i & 1) * 8192;
        const uint32_t* Ws = Xs + 4096;

#pragma unroll
        for (int kk = 0; kk < 32; kk += 8) {
            uint32_t af[4][4], bf[4][2];
#pragma unroll
            for (int mt = 0; mt < 4; mt++) {
                int ra = wm0 + mt * 16 + gid;
                uint32_t sw = (ra & 7) << 2;
                uint32_t c0 = (uint32_t)(kk + tig) ^ sw;
                uint32_t c1 = (uint32_t)(kk + tig + 4) ^ sw;
                af[mt][0] = Xs[ra * 32 + c0];
                af[mt][1] = Xs[(ra + 8) * 32 + c0];
                af[mt][2] = Xs[ra * 32 + c1];
                af[mt][3] = Xs[(ra + 8) * 32 + c1];
            }
#pragma unroll
            for (int nt = 0; nt < 4; nt++) {
                int rb = wn0 + nt * 8 + gid;
                uint32_t sw = (rb & 7) << 2;
                bf[nt][0] = Ws[rb * 32 + ((uint32_t)(kk + tig) ^ sw)];
                bf[nt][1] = Ws[rb * 32 + ((uint32_t)(kk + tig + 4) ^ sw)];
            }
#pragma unroll
            for (int mt = 0; mt < 4; mt++)
#pragma unroll
                for (int nt = 0; nt < 4; nt++)
                    mma_tf32(acc[mt][nt], af[mt], bf[nt][0], bf[nt][1]);
        }
        __syncthreads();
        if (i < 14) issue((i + 2) * 32, i & 1);
    }
}

// ---------------------------------------------------------------------------
// QKV projection: z=0 -> Q (hi/lo split halves, [pair][a][d]),
//                 z=1 -> K (hi halves, [pair][a][d]),
//                 z=2 -> V (hi halves, kv-pair packed [pair][a/2][d][2]).
// ---------------------------------------------------------------------------
__global__ __launch_bounds__(256, 2) void gemm_qkv(
    const float* __restrict__ X,
    const float* __restrict__ W0, const float* __restrict__ W1,
    const float* __restrict__ W2,
    const float* __restrict__ b0p, const float* __restrict__ b1p,
    const float* __restrict__ b2p)
{
    extern __shared__ uint32_t smp[];
    const int z = blockIdx.z;
    const float* W    = z == 0 ? W0  : z == 1 ? W1  : W2;
    const float* bias = z == 0 ? b0p : z == 1 ? b1p : b2p;

    const int tid  = threadIdx.x;
    const int warp = tid >> 5;
    const int lane = tid & 31;
    const int gid  = lane >> 2;
    const int tig  = lane & 3;
    const int m0 = blockIdx.x * 128;
    const int n0 = blockIdx.y * 128;
    const int wm0 = (warp & 1) * 64;
    const int wn0 = (warp >> 1) * 32;

    float acc[4][4][4];
#pragma unroll
    for (int mt = 0; mt < 4; mt++)
#pragma unroll
        for (int nt = 0; nt < 4; nt++)
#pragma unroll
            for (int i = 0; i < 4; i++) acc[mt][nt][i] = 0.0f;

    gemm_body(X, W, smp, acc, m0, n0, wm0, wn0, gid, tig);

    uint32_t* qhi_w = (uint32_t*)g_qhi;
    uint32_t* qlo_w = (uint32_t*)g_qlo;
    uint32_t* khi_w = (uint32_t*)g_khi;

#pragma unroll
    for (int mt = 0; mt < 4; mt++) {
        int mr = m0 + wm0 + mt * 16 + gid;
#pragma unroll
        for (int nt = 0; nt < 4; nt++) {
            int nc = n0 + wn0 + nt * 8 + tig * 2;
            float2 b2 = *(const float2*)&bias[nc];
            float v0 = acc[mt][nt][0] + b2.x, v1 = acc[mt][nt][1] + b2.y;
            float v2 = acc[mt][nt][2] + b2.x, v3 = acc[mt][nt][3] + b2.y;
            int h = nc >> 6, d = nc & 63;
            int a0 = mr >> 4;                 // same a for mr and mr+8
            int p0 = (mr & 15) * 8 + h;
            int p1 = ((mr + 8) & 15) * 8 + h;
            size_t w0 = ((size_t)p0 * 1024 + a0) * 32 + (d >> 1);
            size_t w1 = ((size_t)p1 * 1024 + a0) * 32 + (d >> 1);
            if (z == 0) {
                uint32_t hi, lo;
                split_h2(v0, v1, hi, lo);
                qhi_w[w0] = hi; qlo_w[w0] = lo;
                split_h2(v2, v3, hi, lo);
                qhi_w[w1] = hi; qlo_w[w1] = lo;
            } else if (z == 1) {
                khi_w[w0] = pack_h2(v0, v1);
                khi_w[w1] = pack_h2(v2, v3);
            } else {
                int a2 = a0 >> 1, par = a0 & 1;
                size_t h0 = (((size_t)p0 * 512 + a2) * 64 + d) * 2 + par;
                size_t h1 = (((size_t)p1 * 512 + a2) * 64 + d) * 2 + par;
                g_vhi[h0]     = __float2half_rn(v0);
                g_vhi[h0 + 2] = __float2half_rn(v1);
                g_vhi[h1]     = __float2half_rn(v2);
                g_vhi[h1 + 2] = __float2half_rn(v3);
            }
        }
    }
}

// ---------------------------------------------------------------------------
// Output projection: plain fp32 out + bias (inputs pre-rounded).
// ---------------------------------------------------------------------------
__global__ __launch_bounds__(256, 2) void gemm_out(
    const float* __restrict__ X, const float* __restrict__ W,
    const float* __restrict__ bias, float* __restrict__ Y)
{
    extern __shared__ uint32_t smp[];
    const int tid  = threadIdx.x;
    const int warp = tid >> 5;
    const int lane = tid & 31;
    const int gid  = lane >> 2;
    const int tig  = lane & 3;
    const int m0 = blockIdx.x * 128;
    const int n0 = blockIdx.y * 128;
    const int wm0 = (warp & 1) * 64;
    const int wn0 = (warp >> 1) * 32;

    float acc[4][4][4];
#pragma unroll
    for (int mt = 0; mt < 4; mt++)
#pragma unroll
        for (int nt = 0; nt < 4; nt++)
#pragma unroll
            for (int i = 0; i < 4; i++) acc[mt][nt][i] = 0.0f;

    gemm_body(X, W, smp, acc, m0, n0, wm0, wn0, gid, tig);

#pragma unroll
    for (int mt = 0; mt < 4; mt++) {
        int mr = m0 + wm0 + mt * 16 + gid;
#pragma unroll
        for (int nt = 0; nt < 4; nt++) {
            int nc = n0 + wn0 + nt * 8 + tig * 2;
            float2 b2 = *(const float2*)&bias[nc];
            float2 r0 = { acc[mt][nt][0] + b2.x, acc[mt][nt][1] + b2.y };
            *(float2*)&Y[(size_t)mr * 512 + nc] = r0;
            float2 r1 = { acc[mt][nt][2] + b2.x, acc[mt][nt][3] + b2.y };
            *(float2*)&Y[(size_t)(mr + 8) * 512 + nc] = r1;
        }
    }
}

// ---------------------------------------------------------------------------
// fp16 2-term flash attention with cp.async double-buffered K/V.
// K/V arrive pre-converted to half in attention-native layouts.
// grid = (A/128, 128 pairs), 8 warps x 16 q-rows, 2 CTAs/SM.
// Output written tf32-rounded so gemm_out consumes it raw.
// ---------------------------------------------------------------------------
#define KP 36
#define VP 72
#define STG_W 4608      // words per stage (K 64*36 + V 32*72)

__global__ __launch_bounds__(256, 2) void attn_mma(
    const float* __restrict__ rbias,
    float* __restrict__ O)
{
    __shared__ uint32_t sm_kv[2 * STG_W];

    const int tid  = threadIdx.x;
    const int warp = tid >> 5;
    const int lane = tid & 31;
    const int gid  = lane >> 2;
    const int tig  = lane & 3;

    const int pair = blockIdx.y;
    const int b = pair >> 3;
    const int h = pair & 7;
    const int q0 = blockIdx.x * 128;
    const int wm = warp * 16;
    const float scale = 0.125f;

    const uint32_t smem_base = (uint32_t)__cvta_generic_to_shared(sm_kv);
    const char* kg_base = (const char*)(g_khi + (size_t)pair * 1024 * 64);
    const char* vg_base = (const char*)(g_vhi + (size_t)pair * 512 * 128);

    auto issue_kv = [&](int kb, int buf) {
        uint32_t sbase = smem_base + (uint32_t)buf * STG_W * 4u;
        uint32_t vsb   = sbase + 64u * KP * 4u;
        const char* kg = kg_base + (size_t)kb * 128;
        const char* vg = vg_base + (size_t)kb * 128;
#pragma unroll
        for (int it = 0; it < 2; it++) {
            int c = tid + it * 256;
            int r = c >> 3, ch = c & 7;
            cp16(sbase + r * (KP * 4) + ch * 16, kg + r * 128 + ch * 16);
            int r2 = c >> 4, c2 = c & 15;
            cp16(vsb + r2 * (VP * 4) + c2 * 16, vg + r2 * 256 + c2 * 16);
        }
        asm volatile("cp.async.commit_group;" ::: "memory");
    };

    issue_kv(0, 0);
    issue_kv(64, 1);

    // Q fragments from pre-split buffers
    uint32_t qhi[4][4], qlo[4][4];
    {
        const uint32_t* qh = (const uint32_t*)g_qhi;
        const uint32_t* ql = (const uint32_t*)g_qlo;
        size_t base0 = ((size_t)pair * 1024 + q0 + wm + gid) * 32;
        size_t base1 = base0 + 8 * 32;
#pragma unroll
        for (int kt = 0; kt < 4; kt++) {
            size_t c0 = kt * 8 + tig;
            qhi[kt][0] = qh[base0 + c0];     qlo[kt][0] = ql[base0 + c0];
            qhi[kt][1] = qh[base1 + c0];     qlo[kt][1] = ql[base1 + c0];
            qhi[kt][2] = qh[base0 + c0 + 4]; qlo[kt][2] = ql[base0 + c0 + 4];
            qhi[kt][3] = qh[base1 + c0 + 4]; qlo[kt][3] = ql[base1 + c0 + 4];
        }
    }

    float o[8][4];
#pragma unroll
    for (int nt = 0; nt < 8; nt++)
#pragma unroll
        for (int i = 0; i < 4; i++) o[nt][i] = 0.0f;
    float m0r = -1e30f, m1r = -1e30f, l0r = 0.0f, l1r = 0.0f;

    for (int i = 0; i < 16; i++) {
        if (i < 15) { asm volatile("cp.async.wait_group 1;" ::: "memory"); }
        else        { asm volatile("cp.async.wait_group 0;" ::: "memory"); }
        __syncthreads();

        const uint32_t* Khi = sm_kv + (i & 1) * STG_W;
        const uint32_t* Vph = Khi + 64 * KP;
        const int kb = i * 64;

        // ---- S = Q K^T ----
        float s[8][4];
#pragma unroll
        for (int nt = 0; nt < 8; nt++)
#pragma unroll
            for (int ii = 0; ii < 4; ii++) s[nt][ii] = 0.0f;

#pragma unroll
        for (int kt = 0; kt < 4; kt++) {
#pragma unroll
            for (int nt = 0; nt < 8; nt++) {
                int wb = (nt * 8 + gid) * KP + kt * 8 + tig;
                uint32_t bh0 = Khi[wb], bh1 = Khi[wb + 4];
                mma_f16(s[nt], qhi[kt], bh0, bh1);
                mma_f16(s[nt], qlo[kt], bh0, bh1);
            }
        }

        // ---- scale + relation bias ----
        {
            const float* br0 = &rbias[(size_t)(q0 + wm + gid) * A_DIM + kb];
            const float* br1 = br0 + 8 * A_DIM;
#pragma unroll
            for (int nt = 0; nt < 8; nt++) {
                float2 b0 = *(const float2*)&br0[nt * 8 + 2 * tig];
                float2 b1 = *(const float2*)&br1[nt * 8 + 2 * tig];
                s[nt][0] = s[nt][0] * scale + b0.x;
                s[nt][1] = s[nt][1] * scale + b0.y;
                s[nt][2] = s[nt][2] * scale + b1.x;
                s[nt][3] = s[nt][3] * scale + b1.y;
            }
        }

        // ---- online softmax ----
        {
            float mx0 = -1e30f, mx1 = -1e30f;
#pragma unroll
            for (int nt = 0; nt < 8; nt++) {
                mx0 = fmaxf(mx0, fmaxf(s[nt][0], s[nt][1]));
                mx1 = fmaxf(mx1, fmaxf(s[nt][2], s[nt][3]));
            }
            mx0 = fmaxf(mx0, __shfl_xor_sync(0xffffffffu, mx0, 1));
            mx0 = fmaxf(mx0, __shfl_xor_sync(0xffffffffu, mx0, 2));
            mx1 = fmaxf(mx1, __shfl_xor_sync(0xffffffffu, mx1, 1));
            mx1 = fmaxf(mx1, __shfl_xor_sync(0xffffffffu, mx1, 2));

            float mn0 = fmaxf(m0r, mx0);
            float mn1 = fmaxf(m1r, mx1);
            float c0 = __expf(m0r - mn0);
            float c1 = __expf(m1r - mn1);
            m0r = mn0; m1r = mn1;

            float rs0 = 0.0f, rs1 = 0.0f;
#pragma unroll
            for (int nt = 0; nt < 8; nt++) {
                s[nt][0] = __expf(s[nt][0] - mn0);
                s[nt][1] = __expf(s[nt][1] - mn0);
                s[nt][2] = __expf(s[nt][2] - mn1);
                s[nt][3] = __expf(s[nt][3] - mn1);
                rs0 += s[nt][0] + s[nt][1];
                rs1 += s[nt][2] + s[nt][3];
            }
            rs0 += __shfl_xor_sync(0xffffffffu, rs0, 1);
            rs0 += __shfl_xor_sync(0xffffffffu, rs0, 2);
            rs1 += __shfl_xor_sync(0xffffffffu, rs1, 1);
            rs1 += __shfl_xor_sync(0xffffffffu, rs1, 2);

            l0r = l0r * c0 + rs0;
            l1r = l1r * c1 + rs1;
#pragma unroll
            for (int nt = 0; nt < 8; nt++) {
                o[nt][0] *= c0; o[nt][1] *= c0;
                o[nt][2] *= c1; o[nt][3] *= c1;
            }
        }

        // ---- O += P V (P hi+lo from registers, V hi only) ----
#pragma unroll
        for (int j = 0; j < 4; j++) {
            uint32_t ah[4], al[4];
            split_h2(s[2*j][0],   s[2*j][1],   ah[0], al[0]);
            split_h2(s[2*j][2],   s[2*j][3],   ah[1], al[1]);
            split_h2(s[2*j+1][0], s[2*j+1][1], ah[2], al[2]);
            split_h2(s[2*j+1][2], s[2*j+1][3], ah[3], al[3]);
#pragma unroll
            for (int nt = 0; nt < 8; nt++) {
                int wb = (j * 8 + tig) * VP + nt * 8 + gid;
                uint32_t bh0 = Vph[wb], bh1 = Vph[wb + 4 * VP];
                mma_f16(o[nt], ah, bh0, bh1);
                mma_f16(o[nt], al, bh0, bh1);
            }
        }
        __syncthreads();
        if (i < 14) issue_kv((i + 2) * 64, i & 1);
    }

    // ---- normalize + write (tf32-rounded, token-major for output GEMM) ----
    {
        float i0 = 1.0f / l0r, i1 = 1.0f / l1r;
        const int r0g = q0 + wm + gid;
        size_t base0 = (size_t)(r0g * B_DIM + b) * DMODEL + h * HEAD_DIM;
        size_t base1 = base0 + (size_t)8 * B_DIM * DMODEL;
#pragma unroll
        for (int nt = 0; nt < 8; nt++) {
            int c = nt * 8 + 2 * tig;
            float2 r0 = { __uint_as_float(f2tf32(o[nt][0] * i0)),
                          __uint_as_float(f2tf32(o[nt][1] * i0)) };
            float2 r1 = { __uint_as_float(f2tf32(o[nt][2] * i1)),
                          __uint_as_float(f2tf32(o[nt][3] * i1)) };
            *(float2*)&O[base0 + c] = r0;
            *(float2*)&O[base1 + c] = r1;
        }
    }
}

// ---------------------------------------------------------------------------

extern "C" void kernel_launch(void* const* d_in, const int* in_sizes, int n_in,
                              void* d_out, int out_size)
{
    const float* src   = (const float*)d_in[0];
    const float* rbias = (const float*)d_in[1];
    const float* Wq    = (const float*)d_in[2];
    const float* bq    = (const float*)d_in[3];
    const float* Wk    = (const float*)d_in[4];
    const float* bk    = (const float*)d_in[5];
    const float* Wv    = (const float*)d_in[6];
    const float* bv    = (const float*)d_in[7];
    const float* Wo    = (const float*)d_in[8];
    const float* bo    = (const float*)d_in[9];
    float* out = (float*)d_out;

    float *ga, *gx, *gwq, *gwk, *gwv, *gwo;
    cudaGetSymbolAddress((void**)&ga, g_attn);
    cudaGetSymbolAddress((void**)&gx, g_x32);
    cudaGetSymbolAddress((void**)&gwq, g_wq32);
    cudaGetSymbolAddress((void**)&gwk, g_wk32);
    cudaGetSymbolAddress((void**)&gwv, g_wv32);
    cudaGetSymbolAddress((void**)&gwo, g_wo32);

    cudaFuncSetAttribute(gemm_qkv, cudaFuncAttributeMaxDynamicSharedMemorySize, 65536);
    cudaFuncSetAttribute(gemm_out, cudaFuncAttributeMaxDynamicSharedMemorySize, 65536);

    // 1) pre-round inputs to tf32 (keeps GEMM mainloops CVT-free)
    tf32_round_all<<<(NX4 + 4 * NW4 + 255) / 256, 256>>>(
        (const float4*)src, (const float4*)Wq, (const float4*)Wk,
        (const float4*)Wv, (const float4*)Wo,
        (float4*)gx, (float4*)gwq, (float4*)gwk, (float4*)gwv, (float4*)gwo);

    // 2) fused QKV projection (writes attention-native half formats)
    gemm_qkv<<<dim3(128, 4, 3), 256, 65536>>>(gx, gwq, gwk, gwv, bq, bk, bv);

    // 3) attention
    attn_mma<<<dim3(A_DIM / 128, B_DIM * NHEAD), 256>>>(rbias, ga);

    // 4) output projection
    gemm_out<<<dim3(128, 4, 1), 256, 65536>>>(ga, gwo, bo, out);
}

// round 8
// speedup vs baseline: 1.1450x; 1.0929x over previous
#include <cuda_runtime.h>
#include <cuda_fp16.h>
#include <cstdint>

#define A_DIM 1024
#define B_DIM 16
#define DMODEL 512
#define NHEAD 8
#define HEAD_DIM 64
#define NTOK (A_DIM * B_DIM)   // 16384

#define QSCALE 0.18033688011112042f   // 0.125 * log2(e)
#define LOG2E  1.4426950408889634f

// Scratch (allocation-free)
__device__ __half g_qh[NTOK * DMODEL];
__device__ __half g_kh[NTOK * DMODEL];
__device__ __half g_vh[NTOK * DMODEL];
__device__ float  g_attn[NTOK * DMODEL];
__device__ float  g_x32[NTOK * DMODEL];
__device__ float  g_wq32[DMODEL * DMODEL];
__device__ float  g_wk32[DMODEL * DMODEL];
__device__ float  g_wv32[DMODEL * DMODEL];
__device__ float  g_wo32[DMODEL * DMODEL];
__device__ float  g_rb2[A_DIM * A_DIM];

__device__ __forceinline__ uint32_t f2tf32(float f) {
    uint32_t r;
    asm("cvt.rna.tf32.f32 %0, %1;" : "=r"(r) : "f"(f));
    return r;
}

__device__ __forceinline__ float ex2(float x) {
    float r;
    asm("ex2.approx.ftz.f32 %0, %1;" : "=f"(r) : "f"(x));
    return r;
}

__device__ __forceinline__ void mma_tf32(float* c, const uint32_t* a,
                                         uint32_t b0, uint32_t b1) {
    asm volatile(
        "mma.sync.aligned.m16n8k8.row.col.f32.tf32.tf32.f32 "
        "{%0,%1,%2,%3}, {%4,%5,%6,%7}, {%8,%9}, {%0,%1,%2,%3};"
        : "+f"(c[0]), "+f"(c[1]), "+f"(c[2]), "+f"(c[3])
        : "r"(a[0]), "r"(a[1]), "r"(a[2]), "r"(a[3]), "r"(b0), "r"(b1));
}

__device__ __forceinline__ void mma_f16(float* c, const uint32_t* a,
                                        uint32_t b0, uint32_t b1) {
    asm volatile(
        "mma.sync.aligned.m16n8k16.row.col.f32.f16.f16.f32 "
        "{%0,%1,%2,%3}, {%4,%5,%6,%7}, {%8,%9}, {%0,%1,%2,%3};"
        : "+f"(c[0]), "+f"(c[1]), "+f"(c[2]), "+f"(c[3])
        : "r"(a[0]), "r"(a[1]), "r"(a[2]), "r"(a[3]), "r"(b0), "r"(b1));
}

__device__ __forceinline__ uint32_t pack_h2(float x, float y) {
    __half2 h = __floats2half2_rn(x, y);
    return *(uint32_t*)&h;
}

__device__ __forceinline__ void cp16(uint32_t dst_s, const void* src) {
    asm volatile("cp.async.cg.shared.global [%0], [%1], 16;"
                 :: "r"(dst_s), "l"(src));
}

// ---------------------------------------------------------------------------
// Prep pass: tf32-round X and the 4 weights; scale rbias by log2(e).
// ---------------------------------------------------------------------------
#define NX4 2097152   // NTOK*DMODEL/4
#define NW4 65536     // DMODEL*DMODEL/4
#define NR4 262144    // A*A/4

__global__ void prep_all(
    const float4* __restrict__ src,
    const float4* __restrict__ wq, const float4* __restrict__ wk,
    const float4* __restrict__ wv, const float4* __restrict__ wo,
    const float4* __restrict__ rb,
    float4* __restrict__ xo,
    float4* __restrict__ wqo, float4* __restrict__ wko,
    float4* __restrict__ wvo, float4* __restrict__ woo,
    float4* __restrict__ rbo)
{
    int idx = blockIdx.x * 256 + threadIdx.x;
    if (idx >= NX4 + 4 * NW4 + NR4) return;
    if (idx >= NX4 + 4 * NW4) {
        int off = idx - NX4 - 4 * NW4;
        float4 v = rb[off];
        v.x *= LOG2E; v.y *= LOG2E; v.z *= LOG2E; v.w *= LOG2E;
        rbo[off] = v;
        return;
    }
    const float4* in; float4* out; int off;
    if (idx < NX4) { in = src; out = xo; off = idx; }
    else {
        int t = idx - NX4;
        int seg = t >> 16;
        off = t & (NW4 - 1);
        in  = seg == 0 ? wq  : seg == 1 ? wk  : seg == 2 ? wv  : wo;
        out = seg == 0 ? wqo : seg == 1 ? wko : seg == 2 ? wvo : woo;
    }
    float4 v = in[off];
    v.x = __uint_as_float(f2tf32(v.x));
    v.y = __uint_as_float(f2tf32(v.y));
    v.z = __uint_as_float(f2tf32(v.z));
    v.w = __uint_as_float(f2tf32(v.w));
    out[off] = v;
}

// ---------------------------------------------------------------------------
// GEMM mainloop (cp.async 2-stage, pre-rounded tf32 inputs, unrolled x2 so
// each stage's smem pointers are compile-time constants).
// BM=128, BN=128, BK=32; 8 warps, warp tile 64x32; dyn smem 64 KB.
// ---------------------------------------------------------------------------
__device__ __forceinline__ void gemm_body(
    const float* __restrict__ X, const float* __restrict__ W,
    uint32_t* smp, float acc[4][4][4],
    int m0, int n0, int wm0, int wn0, int gid, int tig)
{
    const int tid = threadIdx.x;
    const int lr  = tid >> 3;
    const int lc4 = (tid & 7) * 4;
    const uint32_t smem_base = (uint32_t)__cvta_generic_to_shared(smp);

    auto issue = [&](int k0, uint32_t buf_off) {
        uint32_t xb = smem_base + buf_off;
        uint32_t wb = xb + 4096u * 4u;
#pragma unroll
        for (int it = 0; it < 4; it++) {
            int rr = lr + it * 32;
            uint32_t cb = (uint32_t)lc4 ^ ((rr & 7) << 2);
            cp16(xb + (rr * 32 + cb) * 4, &X[(size_t)(m0 + rr) * 512 + k0 + lc4]);
            cp16(wb + (rr * 32 + cb) * 4, &W[(size_t)(n0 + rr) * 512 + k0 + lc4]);
        }
        asm volatile("cp.async.commit_group;" ::: "memory");
    };

    auto compute = [&](const uint32_t* Xs, const uint32_t* Ws) {
#pragma unroll
        for (int kk = 0; kk < 32; kk += 8) {
            uint32_t af[4][4], bf[4][2];
#pragma unroll
            for (int mt = 0; mt < 4; mt++) {
                int ra = wm0 + mt * 16 + gid;
                uint32_t sw = (ra & 7) << 2;
                uint32_t c0 = (uint32_t)(kk + tig) ^ sw;
                uint32_t c1 = c0 ^ 4u;
                af[mt][0] = Xs[ra * 32 + c0];
                af[mt][1] = Xs[(ra + 8) * 32 + c0];
                af[mt][2] = Xs[ra * 32 + c1];
                af[mt][3] = Xs[(ra + 8) * 32 + c1];
            }
#pragma unroll
            for (int nt = 0; nt < 4; nt++) {
                int rb = wn0 + nt * 8 + gid;
                uint32_t sw = (rb & 7) << 2;
                uint32_t c0 = (uint32_t)(kk + tig) ^ sw;
                bf[nt][0] = Ws[rb * 32 + c0];
                bf[nt][1] = Ws[rb * 32 + (c0 ^ 4u)];
            }
#pragma unroll
            for (int mt = 0; mt < 4; mt++)
#pragma unroll
                for (int nt = 0; nt < 4; nt++)
                    mma_tf32(acc[mt][nt], af[mt], bf[nt][0], bf[nt][1]);
        }
    };

    issue(0, 0);
    issue(32, 32768u);

    for (int ii = 0; ii < 8; ii++) {
        const int i0 = 2 * ii;
        asm volatile("cp.async.wait_group 1;" ::: "memory");
        __syncthreads();
        compute(smp, smp + 4096);
        __syncthreads();
        if (i0 < 14) issue((i0 + 2) * 32, 0);

        const int i1 = i0 + 1;
        if (i1 < 15) { asm volatile("cp.async.wait_group 1;" ::: "memory"); }
        else         { asm volatile("cp.async.wait_group 0;" ::: "memory"); }
        __syncthreads();
        compute(smp + 8192, smp + 12288);
        __syncthreads();
        if (i1 < 14) issue((i1 + 2) * 32, 32768u);
    }
}

// ---------------------------------------------------------------------------
// QKV projection: z=0 -> Q (fp16, pre-scaled by 0.125*log2e, [pair][a][d]),
//                 z=1 -> K (fp16, [pair][a][d]),
//                 z=2 -> V (fp16, kv-pair packed [pair][a/2][d][2]).
// ---------------------------------------------------------------------------
__global__ __launch_bounds__(256, 2) void gemm_qkv(
    const float* __restrict__ X,
    const float* __restrict__ W0, const float* __restrict__ W1,
    const float* __restrict__ W2,
    const float* __restrict__ b0p, const float* __restrict__ b1p,
    const float* __restrict__ b2p)
{
    extern __shared__ uint32_t smp[];
    const int z = blockIdx.z;
    const float* W    = z == 0 ? W0  : z == 1 ? W1  : W2;
    const float* bias = z == 0 ? b0p : z == 1 ? b1p : b2p;

    const int tid  = threadIdx.x;
    const int warp = tid >> 5;
    const int lane = tid & 31;
    const int gid  = lane >> 2;
    const int tig  = lane & 3;
    const int m0 = blockIdx.x * 128;
    const int n0 = blockIdx.y * 128;
    const int wm0 = (warp & 1) * 64;
    const int wn0 = (warp >> 1) * 32;

    float acc[4][4][4];
#pragma unroll
    for (int mt = 0; mt < 4; mt++)
#pragma unroll
        for (int nt = 0; nt < 4; nt++)
#pragma unroll
            for (int i = 0; i < 4; i++) acc[mt][nt][i] = 0.0f;

    gemm_body(X, W, smp, acc, m0, n0, wm0, wn0, gid, tig);

    uint32_t* qh_w = (uint32_t*)g_qh;
    uint32_t* kh_w = (uint32_t*)g_kh;

#pragma unroll
    for (int mt = 0; mt < 4; mt++) {
        int mr = m0 + wm0 + mt * 16 + gid;
#pragma unroll
        for (int nt = 0; nt < 4; nt++) {
            int nc = n0 + wn0 + nt * 8 + tig * 2;
            float2 b2 = *(const float2*)&bias[nc];
            float v0 = acc[mt][nt][0] + b2.x, v1 = acc[mt][nt][1] + b2.y;
            float v2 = acc[mt][nt][2] + b2.x, v3 = acc[mt][nt][3] + b2.y;
            int h = nc >> 6, d = nc & 63;
            int a0 = mr >> 4;
            int p0 = (mr & 15) * 8 + h;
            int p1 = ((mr + 8) & 15) * 8 + h;
            size_t w0 = ((size_t)p0 * 1024 + a0) * 32 + (d >> 1);
            size_t w1 = ((size_t)p1 * 1024 + a0) * 32 + (d >> 1);
            if (z == 0) {
                qh_w[w0] = pack_h2(v0 * QSCALE, v1 * QSCALE);
                qh_w[w1] = pack_h2(v2 * QSCALE, v3 * QSCALE);
            } else if (z == 1) {
                kh_w[w0] = pack_h2(v0, v1);
                kh_w[w1] = pack_h2(v2, v3);
            } else {
                int a2 = a0 >> 1, par = a0 & 1;
                size_t h0 = (((size_t)p0 * 512 + a2) * 64 + d) * 2 + par;
                size_t h1 = (((size_t)p1 * 512 + a2) * 64 + d) * 2 + par;
                g_vh[h0]     = __float2half_rn(v0);
                g_vh[h0 + 2] = __float2half_rn(v1);
                g_vh[h1]     = __float2half_rn(v2);
                g_vh[h1 + 2] = __float2half_rn(v3);
            }
        }
    }
}

// ---------------------------------------------------------------------------
// Output projection: plain fp32 out + bias (inputs pre-rounded).
// ---------------------------------------------------------------------------
__global__ __launch_bounds__(256, 2) void gemm_out(
    const float* __restrict__ X, const float* __restrict__ W,
    const float* __restrict__ bias, float* __restrict__ Y)
{
    extern __shared__ uint32_t smp[];
    const int tid  = threadIdx.x;
    const int warp = tid >> 5;
    const int lane = tid & 31;
    const int gid  = lane >> 2;
    const int tig  = lane & 3;
    const int m0 = blockIdx.x * 128;
    const int n0 = blockIdx.y * 128;
    const int wm0 = (warp & 1) * 64;
    const int wn0 = (warp >> 1) * 32;

    float acc[4][4][4];
#pragma unroll
    for (int mt = 0; mt < 4; mt++)
#pragma unroll
        for (int nt = 0; nt < 4; nt++)
#pragma unroll
            for (int i = 0; i < 4; i++) acc[mt][nt][i] = 0.0f;

    gemm_body(X, W, smp, acc, m0, n0, wm0, wn0, gid, tig);

#pragma unroll
    for (int mt = 0; mt < 4; mt++) {
        int mr = m0 + wm0 + mt * 16 + gid;
#pragma unroll
        for (int nt = 0; nt < 4; nt++) {
            int nc = n0 + wn0 + nt * 8 + tig * 2;
            float2 b2 = *(const float2*)&bias[nc];
            float2 r0 = { acc[mt][nt][0] + b2.x, acc[mt][nt][1] + b2.y };
            *(float2*)&Y[(size_t)mr * 512 + nc] = r0;
            float2 r1 = { acc[mt][nt][2] + b2.x, acc[mt][nt][3] + b2.y };
            *(float2*)&Y[(size_t)(mr + 8) * 512 + nc] = r1;
        }
    }
}

// ---------------------------------------------------------------------------
// Pure-fp16 flash attention (1-term), exp2-domain softmax, cp.async
// double-buffered K/V in producer-native layouts. Q pre-scaled by
// 0.125*log2e; rbias pre-scaled by log2e.
// grid = (A/128, 128 pairs), 8 warps x 16 q-rows, 2 CTAs/SM.
// ---------------------------------------------------------------------------
#define KP 36
#define VP 72
#define STG_W 4608      // words per stage (K 64*36 + V 32*72)

__global__ __launch_bounds__(256, 2) void attn_mma(
    const float* __restrict__ rbias2,
    float* __restrict__ O)
{
    __shared__ uint32_t sm_kv[2 * STG_W];

    const int tid  = threadIdx.x;
    const int warp = tid >> 5;
    const int lane = tid & 31;
    const int gid  = lane >> 2;
    const int tig  = lane & 3;

    const int pair = blockIdx.y;
    const int b = pair >> 3;
    const int h = pair & 7;
    const int q0 = blockIdx.x * 128;
    const int wm = warp * 16;

    const uint32_t smem_base = (uint32_t)__cvta_generic_to_shared(sm_kv);
    const char* kg_base = (const char*)(g_kh + (size_t)pair * 1024 * 64);
    const char* vg_base = (const char*)(g_vh + (size_t)pair * 512 * 128);

    auto issue_kv = [&](int kb, uint32_t buf_off) {
        uint32_t sbase = smem_base + buf_off;
        uint32_t vsb   = sbase + 64u * KP * 4u;
        const char* kg = kg_base + (size_t)kb * 128;
        const char* vg = vg_base + (size_t)kb * 128;
#pragma unroll
        for (int it = 0; it < 2; it++) {
            int c = tid + it * 256;
            int r = c >> 3, ch = c & 7;
            cp16(sbase + r * (KP * 4) + ch * 16, kg + r * 128 + ch * 16);
            int r2 = c >> 4, c2 = c & 15;
            cp16(vsb + r2 * (VP * 4) + c2 * 16, vg + r2 * 256 + c2 * 16);
        }
        asm volatile("cp.async.commit_group;" ::: "memory");
    };

    issue_kv(0, 0);
    issue_kv(64, STG_W * 4u);

    // Q fragments (pre-scaled fp16)
    uint32_t qf[4][4];
    {
        const uint32_t* qh = (const uint32_t*)g_qh;
        size_t base0 = ((size_t)pair * 1024 + q0 + wm + gid) * 32;
        size_t base1 = base0 + 8 * 32;
#pragma unroll
        for (int kt = 0; kt < 4; kt++) {
            size_t c0 = kt * 8 + tig;
            qf[kt][0] = qh[base0 + c0];
            qf[kt][1] = qh[base1 + c0];
            qf[kt][2] = qh[base0 + c0 + 4];
            qf[kt][3] = qh[base1 + c0 + 4];
        }
    }

    float o[8][4];
#pragma unroll
    for (int nt = 0; nt < 8; nt++)
#pragma unroll
        for (int i = 0; i < 4; i++) o[nt][i] = 0.0f;
    float m0r = -1e30f, m1r = -1e30f, l0r = 0.0f, l1r = 0.0f;

    const float* brow = &rbias2[(size_t)(q0 + wm + gid) * A_DIM];

    auto proc = [&](int i, const uint32_t* Khi, uint32_t buf_off) {
        if (i < 15) { asm volatile("cp.async.wait_group 1;" ::: "memory"); }
        else        { asm volatile("cp.async.wait_group 0;" ::: "memory"); }
        __syncthreads();

        const uint32_t* Vph = Khi + 64 * KP;
        const int kb = i * 64;

        // ---- S = Q K^T (logits already in log2 domain) ----
        float s[8][4];
#pragma unroll
        for (int nt = 0; nt < 8; nt++)
#pragma unroll
            for (int ii2 = 0; ii2 < 4; ii2++) s[nt][ii2] = 0.0f;

#pragma unroll
        for (int kt = 0; kt < 4; kt++) {
#pragma unroll
            for (int nt = 0; nt < 8; nt++) {
                int wb = (nt * 8 + gid) * KP + kt * 8 + tig;
                mma_f16(s[nt], qf[kt], Khi[wb], Khi[wb + 4]);
            }
        }

        // ---- + relation bias (pre-scaled by log2e) ----
        {
            const float* br0 = brow + kb;
            const float* br1 = br0 + 8 * A_DIM;
#pragma unroll
            for (int nt = 0; nt < 8; nt++) {
                float2 b0 = *(const float2*)&br0[nt * 8 + 2 * tig];
                float2 b1 = *(const float2*)&br1[nt * 8 + 2 * tig];
                s[nt][0] += b0.x;  s[nt][1] += b0.y;
                s[nt][2] += b1.x;  s[nt][3] += b1.y;
            }
        }

        // ---- online softmax (base-2) ----
        {
            float mx0 = -1e30f, mx1 = -1e30f;
#pragma unroll
            for (int nt = 0; nt < 8; nt++) {
                mx0 = fmaxf(mx0, fmaxf(s[nt][0], s[nt][1]));
                mx1 = fmaxf(mx1, fmaxf(s[nt][2], s[nt][3]));
            }
            mx0 = fmaxf(mx0, __shfl_xor_sync(0xffffffffu, mx0, 1));
            mx0 = fmaxf(mx0, __shfl_xor_sync(0xffffffffu, mx0, 2));
            mx1 = fmaxf(mx1, __shfl_xor_sync(0xffffffffu, mx1, 1));
            mx1 = fmaxf(mx1, __shfl_xor_sync(0xffffffffu, mx1, 2));

            float mn0 = fmaxf(m0r, mx0);
            float mn1 = fmaxf(m1r, mx1);
            float c0 = ex2(m0r - mn0);
            float c1 = ex2(m1r - mn1);
            m0r = mn0; m1r = mn1;

            float rs0 = 0.0f, rs1 = 0.0f;
#pragma unroll
            for (int nt = 0; nt < 8; nt++) {
                s[nt][0] = ex2(s[nt][0] - mn0);
                s[nt][1] = ex2(s[nt][1] - mn0);
                s[nt][2] = ex2(s[nt][2] - mn1);
                s[nt][3] = ex2(s[nt][3] - mn1);
                rs0 += s[nt][0] + s[nt][1];
                rs1 += s[nt][2] + s[nt][3];
            }
            rs0 += __shfl_xor_sync(0xffffffffu, rs0, 1);
            rs0 += __shfl_xor_sync(0xffffffffu, rs0, 2);
            rs1 += __shfl_xor_sync(0xffffffffu, rs1, 1);
            rs1 += __shfl_xor_sync(0xffffffffu, rs1, 2);

            l0r = l0r * c0 + rs0;
            l1r = l1r * c1 + rs1;
#pragma unroll
            for (int nt = 0; nt < 8; nt++) {
                o[nt][0] *= c0; o[nt][1] *= c0;
                o[nt][2] *= c1; o[nt][3] *= c1;
            }
        }

        // ---- O += P V (both fp16 1-term) ----
#pragma unroll
        for (int j = 0; j < 4; j++) {
            uint32_t ah[4];
            ah[0] = pack_h2(s[2*j][0],   s[2*j][1]);
            ah[1] = pack_h2(s[2*j][2],   s[2*j][3]);
            ah[2] = pack_h2(s[2*j+1][0], s[2*j+1][1]);
            ah[3] = pack_h2(s[2*j+1][2], s[2*j+1][3]);
#pragma unroll
            for (int nt = 0; nt < 8; nt++) {
                int wb = (j * 8 + tig) * VP + nt * 8 + gid;
                mma_f16(o[nt], ah, Vph[wb], Vph[wb + 4 * VP]);
            }
        }
        __syncthreads();
        if (i < 14) issue_kv((i + 2) * 64, buf_off);
    };

    for (int ii = 0; ii < 8; ii++) {
        proc(2 * ii,     sm_kv,         0);
        proc(2 * ii + 1, sm_kv + STG_W, STG_W * 4u);
    }

    // ---- normalize + write (tf32-rounded, token-major for output GEMM) ----
    {
        float i0 = 1.0f / l0r, i1 = 1.0f / l1r;
        const int r0g = q0 + wm + gid;
        size_t base0 = (size_t)(r0g * B_DIM + b) * DMODEL + h * HEAD_DIM;
        size_t base1 = base0 + (size_t)8 * B_DIM * DMODEL;
#pragma unroll
        for (int nt = 0; nt < 8; nt++) {
            int c = nt * 8 + 2 * tig;
            float2 r0 = { __uint_as_float(f2tf32(o[nt][0] * i0)),
                          __uint_as_float(f2tf32(o[nt][1] * i0)) };
            float2 r1 = { __uint_as_float(f2tf32(o[nt][2] * i1)),
                          __uint_as_float(f2tf32(o[nt][3] * i1)) };
            *(float2*)&O[base0 + c] = r0;
            *(float2*)&O[base1 + c] = r1;
        }
    }
}

// ---------------------------------------------------------------------------

extern "C" void kernel_launch(void* const* d_in, const int* in_sizes, int n_in,
                              void* d_out, int out_size)
{
    const float* src   = (const float*)d_in[0];
    const float* rbias = (const float*)d_in[1];
    const float* Wq    = (const float*)d_in[2];
    const float* bq    = (const float*)d_in[3];
    const float* Wk    = (const float*)d_in[4];
    const float* bk    = (const float*)d_in[5];
    const float* Wv    = (const float*)d_in[6];
    const float* bv    = (const float*)d_in[7];
    const float* Wo    = (const float*)d_in[8];
    const float* bo    = (const float*)d_in[9];
    float* out = (float*)d_out;

    float *ga, *gx, *gwq, *gwk, *gwv, *gwo, *grb;
    cudaGetSymbolAddress((void**)&ga, g_attn);
    cudaGetSymbolAddress((void**)&gx, g_x32);
    cudaGetSymbolAddress((void**)&gwq, g_wq32);
    cudaGetSymbolAddress((void**)&gwk, g_wk32);
    cudaGetSymbolAddress((void**)&gwv, g_wv32);
    cudaGetSymbolAddress((void**)&gwo, g_wo32);
    cudaGetSymbolAddress((void**)&grb, g_rb2);

    cudaFuncSetAttribute(gemm_qkv, cudaFuncAttributeMaxDynamicSharedMemorySize, 65536);
    cudaFuncSetAttribute(gemm_out, cudaFuncAttributeMaxDynamicSharedMemorySize, 65536);

    // 1) prep: tf32-round X/W, scale rbias by log2e
    prep_all<<<(NX4 + 4 * NW4 + NR4 + 255) / 256, 256>>>(
        (const float4*)src, (const float4*)Wq, (const float4*)Wk,
        (const float4*)Wv, (const float4*)Wo, (const float4*)rbias,
        (float4*)gx, (float4*)gwq, (float4*)gwk, (float4*)gwv, (float4*)gwo,
        (float4*)grb);

    // 2) fused QKV projection (writes attention-native fp16 formats)
    gemm_qkv<<<dim3(128, 4, 3), 256, 65536>>>(gx, gwq, gwk, gwv, bq, bk, bv);

    // 3) attention
    attn_mma<<<dim3(A_DIM / 128, B_DIM * NHEAD), 256>>>(grb, ga);

    // 4) output projection
    gemm_out<<<dim3(128, 4, 1), 256, 65536>>>(ga, gwo, bo, out);
}

// round 9
// speedup vs baseline: 1.2517x; 1.0932x over previous
#include <cuda_runtime.h>
#include <cuda_fp16.h>
#include <cstdint>

#define A_DIM 1024
#define B_DIM 16
#define DMODEL 512
#define NHEAD 8
#define HEAD_DIM 64
#define NTOK (A_DIM * B_DIM)   // 16384

#define QSCALE 0.18033688011112042f   // 0.125 * log2(e)
#define LOG2E  1.4426950408889634f

// Scratch (allocation-free)
__device__ __half g_xh[NTOK * DMODEL];   // src hi
__device__ __half g_xl[NTOK * DMODEL];   // src lo
__device__ __half g_ah[NTOK * DMODEL];   // attn-out hi
__device__ __half g_al[NTOK * DMODEL];   // attn-out lo
__device__ __half g_qh[NTOK * DMODEL];
__device__ __half g_kh[NTOK * DMODEL];
__device__ __half g_vh[NTOK * DMODEL];
__device__ __half g_wqh[DMODEL * DMODEL];
__device__ __half g_wkh[DMODEL * DMODEL];
__device__ __half g_wvh[DMODEL * DMODEL];
__device__ __half g_woh[DMODEL * DMODEL];
__device__ float  g_rb2[A_DIM * A_DIM];

__device__ __forceinline__ float ex2(float x) {
    float r;
    asm("ex2.approx.ftz.f32 %0, %1;" : "=f"(r) : "f"(x));
    return r;
}

__device__ __forceinline__ void mma_f16(float* c, const uint32_t* a,
                                        uint32_t b0, uint32_t b1) {
    asm volatile(
        "mma.sync.aligned.m16n8k16.row.col.f32.f16.f16.f32 "
        "{%0,%1,%2,%3}, {%4,%5,%6,%7}, {%8,%9}, {%0,%1,%2,%3};"
        : "+f"(c[0]), "+f"(c[1]), "+f"(c[2]), "+f"(c[3])
        : "r"(a[0]), "r"(a[1]), "r"(a[2]), "r"(a[3]), "r"(b0), "r"(b1));
}

__device__ __forceinline__ uint32_t pack_h2(float x, float y) {
    __half2 h = __floats2half2_rn(x, y);
    return *(uint32_t*)&h;
}

__device__ __forceinline__ void split_h2(float x, float y,
                                         uint32_t& hi, uint32_t& lo) {
    __half2 h = __floats2half2_rn(x, y);
    float rx = x - __half2float(__low2half(h));
    float ry = y - __half2float(__high2half(h));
    __half2 l = __floats2half2_rn(rx, ry);
    hi = *(uint32_t*)&h;
    lo = *(uint32_t*)&l;
}

__device__ __forceinline__ void cp16(uint32_t dst_s, const void* src) {
    asm volatile("cp.async.cg.shared.global [%0], [%1], 16;"
                 :: "r"(dst_s), "l"(src));
}

// ---------------------------------------------------------------------------
// Prep: split src to fp16 hi/lo; round W's to fp16; scale rbias by log2e.
// ---------------------------------------------------------------------------
#define NX4 2097152   // NTOK*DMODEL/4
#define NW4 65536     // DMODEL*DMODEL/4
#define NR4 262144    // A*A/4

__global__ void prep_all(
    const float4* __restrict__ src,
    const float4* __restrict__ wq, const float4* __restrict__ wk,
    const float4* __restrict__ wv, const float4* __restrict__ wo,
    const float4* __restrict__ rb,
    float4* __restrict__ rbo)
{
    int idx = blockIdx.x * 256 + threadIdx.x;
    if (idx >= NX4 + 4 * NW4 + NR4) return;
    if (idx < NX4) {
        float4 v = src[idx];
        uint2 h, l;
        split_h2(v.x, v.y, h.x, l.x);
        split_h2(v.z, v.w, h.y, l.y);
        ((uint2*)g_xh)[idx] = h;
        ((uint2*)g_xl)[idx] = l;
        return;
    }
    if (idx < NX4 + 4 * NW4) {
        int t = idx - NX4;
        int seg = t >> 16;
        int off = t & (NW4 - 1);
        const float4* in = seg == 0 ? wq : seg == 1 ? wk : seg == 2 ? wv : wo;
        __half* out = seg == 0 ? g_wqh : seg == 1 ? g_wkh : seg == 2 ? g_wvh : g_woh;
        float4 v = in[off];
        uint2 h;
        h.x = pack_h2(v.x, v.y);
        h.y = pack_h2(v.z, v.w);
        ((uint2*)out)[off] = h;
        return;
    }
    int off = idx - NX4 - 4 * NW4;
    float4 v = rb[off];
    v.x *= LOG2E; v.y *= LOG2E; v.z *= LOG2E; v.w *= LOG2E;
    rbo[off] = v;
}

// ---------------------------------------------------------------------------
// fp16 2-term GEMM mainloop: Y = X @ W^T, X exact (hi+lo), W fp16.
// BM=128, BN=128, BK=32; 8 warps, warp tile 64x32; m16n8k16.
// Smem per stage: Xh[128][20w] + Xl[128][20w] + Ws[128][20w] = 30720 B
// (pitch 20 words -> conflict-free fragment LDS; rows 80B, 16B-aligned).
// 2 stages = 61440 B dynamic smem.
// ---------------------------------------------------------------------------
#define GP 20         // row pitch in 32-bit words
#define TILE_W 2560   // 128 * GP words per tile
#define STAGE_W 7680  // 3 tiles per stage

__device__ __forceinline__ void gemm_body_f16(
    const __half* __restrict__ Xh, const __half* __restrict__ Xl,
    const __half* __restrict__ W,
    uint32_t* smp, float acc[4][4][4],
    int m0, int n0, int wm0, int wn0, int gid, int tig)
{
    const int tid = threadIdx.x;
    const uint32_t smem_base = (uint32_t)__cvta_generic_to_shared(smp);

    auto issue = [&](int k0, uint32_t buf_off) {
        uint32_t base = smem_base + buf_off;
#pragma unroll
        for (int it = 0; it < 2; it++) {
            int c = tid + it * 256;          // 0..511
            int row = c >> 2, ch = c & 3;
            uint32_t dst = base + row * (GP * 4) + ch * 16;
            size_t gsx = (size_t)(m0 + row) * 1024 + k0 * 2 + ch * 16;
            cp16(dst,                 (const char*)Xh + gsx);
            cp16(dst + TILE_W * 4,    (const char*)Xl + gsx);
            size_t gsw = (size_t)(n0 + row) * 1024 + k0 * 2 + ch * 16;
            cp16(dst + 2 * TILE_W * 4, (const char*)W + gsw);
        }
        asm volatile("cp.async.commit_group;" ::: "memory");
    };

    auto compute = [&](const uint32_t* Sx) {
        const uint32_t* Sl = Sx + TILE_W;
        const uint32_t* Sw = Sx + 2 * TILE_W;
#pragma unroll
        for (int kc = 0; kc < 2; kc++) {
            uint32_t ah[4][4], al[4][4], bf[4][2];
#pragma unroll
            for (int mt = 0; mt < 4; mt++) {
                int w = (wm0 + mt * 16 + gid) * GP + kc * 8 + tig;
                ah[mt][0] = Sx[w];           ah[mt][1] = Sx[w + 8 * GP];
                ah[mt][2] = Sx[w + 4];       ah[mt][3] = Sx[w + 8 * GP + 4];
                al[mt][0] = Sl[w];           al[mt][1] = Sl[w + 8 * GP];
                al[mt][2] = Sl[w + 4];       al[mt][3] = Sl[w + 8 * GP + 4];
            }
#pragma unroll
            for (int nt = 0; nt < 4; nt++) {
                int w = (wn0 + nt * 8 + gid) * GP + kc * 8 + tig;
                bf[nt][0] = Sw[w];
                bf[nt][1] = Sw[w + 4];
            }
#pragma unroll
            for (int mt = 0; mt < 4; mt++)
#pragma unroll
                for (int nt = 0; nt < 4; nt++) {
                    mma_f16(acc[mt][nt], ah[mt], bf[nt][0], bf[nt][1]);
                    mma_f16(acc[mt][nt], al[mt], bf[nt][0], bf[nt][1]);
                }
        }
    };

    issue(0, 0);
    issue(32, STAGE_W * 4u);

    for (int ii = 0; ii < 8; ii++) {
        const int i0 = 2 * ii;
        asm volatile("cp.async.wait_group 1;" ::: "memory");
        __syncthreads();
        compute(smp);
        __syncthreads();
        if (i0 < 14) issue((i0 + 2) * 32, 0);

        const int i1 = i0 + 1;
        if (i1 < 15) { asm volatile("cp.async.wait_group 1;" ::: "memory"); }
        else         { asm volatile("cp.async.wait_group 0;" ::: "memory"); }
        __syncthreads();
        compute(smp + STAGE_W);
        __syncthreads();
        if (i1 < 14) issue((i1 + 2) * 32, STAGE_W * 4u);
    }
}

// ---------------------------------------------------------------------------
// QKV projection (fp16 2-term): z=0 -> Q (scaled), z=1 -> K, z=2 -> V packed.
// ---------------------------------------------------------------------------
__global__ __launch_bounds__(256, 2) void gemm_qkv(
    const float* __restrict__ b0p, const float* __restrict__ b1p,
    const float* __restrict__ b2p)
{
    extern __shared__ uint32_t smp[];
    const int z = blockIdx.z;
    const __half* W    = z == 0 ? g_wqh : z == 1 ? g_wkh : g_wvh;
    const float* bias  = z == 0 ? b0p   : z == 1 ? b1p   : b2p;

    const int tid  = threadIdx.x;
    const int warp = tid >> 5;
    const int lane = tid & 31;
    const int gid  = lane >> 2;
    const int tig  = lane & 3;
    const int m0 = blockIdx.x * 128;
    const int n0 = blockIdx.y * 128;
    const int wm0 = (warp & 1) * 64;
    const int wn0 = (warp >> 1) * 32;

    float acc[4][4][4];
#pragma unroll
    for (int mt = 0; mt < 4; mt++)
#pragma unroll
        for (int nt = 0; nt < 4; nt++)
#pragma unroll
            for (int i = 0; i < 4; i++) acc[mt][nt][i] = 0.0f;

    gemm_body_f16(g_xh, g_xl, W, smp, acc, m0, n0, wm0, wn0, gid, tig);

    uint32_t* qh_w = (uint32_t*)g_qh;
    uint32_t* kh_w = (uint32_t*)g_kh;

#pragma unroll
    for (int mt = 0; mt < 4; mt++) {
        int mr = m0 + wm0 + mt * 16 + gid;
#pragma unroll
        for (int nt = 0; nt < 4; nt++) {
            int nc = n0 + wn0 + nt * 8 + tig * 2;
            float2 b2 = *(const float2*)&bias[nc];
            float v0 = acc[mt][nt][0] + b2.x, v1 = acc[mt][nt][1] + b2.y;
            float v2 = acc[mt][nt][2] + b2.x, v3 = acc[mt][nt][3] + b2.y;
            int h = nc >> 6, d = nc & 63;
            int a0 = mr >> 4;
            int p0 = (mr & 15) * 8 + h;
            int p1 = ((mr + 8) & 15) * 8 + h;
            size_t w0 = ((size_t)p0 * 1024 + a0) * 32 + (d >> 1);
            size_t w1 = ((size_t)p1 * 1024 + a0) * 32 + (d >> 1);
            if (z == 0) {
                qh_w[w0] = pack_h2(v0 * QSCALE, v1 * QSCALE);
                qh_w[w1] = pack_h2(v2 * QSCALE, v3 * QSCALE);
            } else if (z == 1) {
                kh_w[w0] = pack_h2(v0, v1);
                kh_w[w1] = pack_h2(v2, v3);
            } else {
                int a2 = a0 >> 1, par = a0 & 1;
                size_t h0 = (((size_t)p0 * 512 + a2) * 64 + d) * 2 + par;
                size_t h1 = (((size_t)p1 * 512 + a2) * 64 + d) * 2 + par;
                g_vh[h0]     = __float2half_rn(v0);
                g_vh[h0 + 2] = __float2half_rn(v1);
                g_vh[h1]     = __float2half_rn(v2);
                g_vh[h1 + 2] = __float2half_rn(v3);
            }
        }
    }
}

// ---------------------------------------------------------------------------
// Output projection (fp16 2-term): consumes attn-out hi/lo, writes fp32.
// ---------------------------------------------------------------------------
__global__ __launch_bounds__(256, 2) void gemm_out(
    const float* __restrict__ bias, float* __restrict__ Y)
{
    extern __shared__ uint32_t smp[];
    const int tid  = threadIdx.x;
    const int warp = tid >> 5;
    const int lane = tid & 31;
    const int gid  = lane >> 2;
    const int tig  = lane & 3;
    const int m0 = blockIdx.x * 128;
    const int n0 = blockIdx.y * 128;
    const int wm0 = (warp & 1) * 64;
    const int wn0 = (warp >> 1) * 32;

    float acc[4][4][4];
#pragma unroll
    for (int mt = 0; mt < 4; mt++)
#pragma unroll
        for (int nt = 0; nt < 4; nt++)
#pragma unroll
            for (int i = 0; i < 4; i++) acc[mt][nt][i] = 0.0f;

    gemm_body_f16(g_ah, g_al, g_woh, smp, acc, m0, n0, wm0, wn0, gid, tig);

#pragma unroll
    for (int mt = 0; mt < 4; mt++) {
        int mr = m0 + wm0 + mt * 16 + gid;
#pragma unroll
        for (int nt = 0; nt < 4; nt++) {
            int nc = n0 + wn0 + nt * 8 + tig * 2;
            float2 b2 = *(const float2*)&bias[nc];
            float2 r0 = { acc[mt][nt][0] + b2.x, acc[mt][nt][1] + b2.y };
            *(float2*)&Y[(size_t)mr * 512 + nc] = r0;
            float2 r1 = { acc[mt][nt][2] + b2.x, acc[mt][nt][3] + b2.y };
            *(float2*)&Y[(size_t)(mr + 8) * 512 + nc] = r1;
        }
    }
}

// ---------------------------------------------------------------------------
// Pure-fp16 flash attention (1-term), exp2-domain softmax, cp.async
// double-buffered K/V in producer-native layouts. Output written as
// hi/lo fp16 split for the fp16 output GEMM.
// ---------------------------------------------------------------------------
#define KP 36
#define VP 72
#define STG_W 4608      // words per stage (K 64*36 + V 32*72)

__global__ __launch_bounds__(256, 2) void attn_mma(
    const float* __restrict__ rbias2)
{
    __shared__ uint32_t sm_kv[2 * STG_W];

    const int tid  = threadIdx.x;
    const int warp = tid >> 5;
    const int lane = tid & 31;
    const int gid  = lane >> 2;
    const int tig  = lane & 3;

    const int pair = blockIdx.y;
    const int b = pair >> 3;
    const int h = pair & 7;
    const int q0 = blockIdx.x * 128;
    const int wm = warp * 16;

    const uint32_t smem_base = (uint32_t)__cvta_generic_to_shared(sm_kv);
    const char* kg_base = (const char*)(g_kh + (size_t)pair * 1024 * 64);
    const char* vg_base = (const char*)(g_vh + (size_t)pair * 512 * 128);

    auto issue_kv = [&](int kb, uint32_t buf_off) {
        uint32_t sbase = smem_base + buf_off;
        uint32_t vsb   = sbase + 64u * KP * 4u;
        const char* kg = kg_base + (size_t)kb * 128;
        const char* vg = vg_base + (size_t)kb * 128;
#pragma unroll
        for (int it = 0; it < 2; it++) {
            int c = tid + it * 256;
            int r = c >> 3, ch = c & 7;
            cp16(sbase + r * (KP * 4) + ch * 16, kg + r * 128 + ch * 16);
            int r2 = c >> 4, c2 = c & 15;
            cp16(vsb + r2 * (VP * 4) + c2 * 16, vg + r2 * 256 + c2 * 16);
        }
        asm volatile("cp.async.commit_group;" ::: "memory");
    };

    issue_kv(0, 0);
    issue_kv(64, STG_W * 4u);

    // Q fragments (pre-scaled fp16)
    uint32_t qf[4][4];
    {
        const uint32_t* qh = (const uint32_t*)g_qh;
        size_t base0 = ((size_t)pair * 1024 + q0 + wm + gid) * 32;
        size_t base1 = base0 + 8 * 32;
#pragma unroll
        for (int kt = 0; kt < 4; kt++) {
            size_t c0 = kt * 8 + tig;
            qf[kt][0] = qh[base0 + c0];
            qf[kt][1] = qh[base1 + c0];
            qf[kt][2] = qh[base0 + c0 + 4];
            qf[kt][3] = qh[base1 + c0 + 4];
        }
    }

    float o[8][4];
#pragma unroll
    for (int nt = 0; nt < 8; nt++)
#pragma unroll
        for (int i = 0; i < 4; i++) o[nt][i] = 0.0f;
    float m0r = -1e30f, m1r = -1e30f, l0r = 0.0f, l1r = 0.0f;

    const float* brow = &rbias2[(size_t)(q0 + wm + gid) * A_DIM];

    auto proc = [&](int i, const uint32_t* Khi, uint32_t buf_off) {
        if (i < 15) { asm volatile("cp.async.wait_group 1;" ::: "memory"); }
        else        { asm volatile("cp.async.wait_group 0;" ::: "memory"); }
        __syncthreads();

        const uint32_t* Vph = Khi + 64 * KP;
        const int kb = i * 64;

        float s[8][4];
#pragma unroll
        for (int nt = 0; nt < 8; nt++)
#pragma unroll
            for (int ii2 = 0; ii2 < 4; ii2++) s[nt][ii2] = 0.0f;

#pragma unroll
        for (int kt = 0; kt < 4; kt++) {
#pragma unroll
            for (int nt = 0; nt < 8; nt++) {
                int wb = (nt * 8 + gid) * KP + kt * 8 + tig;
                mma_f16(s[nt], qf[kt], Khi[wb], Khi[wb + 4]);
            }
        }

        {
            const float* br0 = brow + kb;
            const float* br1 = br0 + 8 * A_DIM;
#pragma unroll
            for (int nt = 0; nt < 8; nt++) {
                float2 b0 = *(const float2*)&br0[nt * 8 + 2 * tig];
                float2 b1 = *(const float2*)&br1[nt * 8 + 2 * tig];
                s[nt][0] += b0.x;  s[nt][1] += b0.y;
                s[nt][2] += b1.x;  s[nt][3] += b1.y;
            }
        }

        {
            float mx0 = -1e30f, mx1 = -1e30f;
#pragma unroll
            for (int nt = 0; nt < 8; nt++) {
                mx0 = fmaxf(mx0, fmaxf(s[nt][0], s[nt][1]));
                mx1 = fmaxf(mx1, fmaxf(s[nt][2], s[nt][3]));
            }
            mx0 = fmaxf(mx0, __shfl_xor_sync(0xffffffffu, mx0, 1));
            mx0 = fmaxf(mx0, __shfl_xor_sync(0xffffffffu, mx0, 2));
            mx1 = fmaxf(mx1, __shfl_xor_sync(0xffffffffu, mx1, 1));
            mx1 = fmaxf(mx1, __shfl_xor_sync(0xffffffffu, mx1, 2));

            float mn0 = fmaxf(m0r, mx0);
            float mn1 = fmaxf(m1r, mx1);
            float c0 = ex2(m0r - mn0);
            float c1 = ex2(m1r - mn1);
            m0r = mn0; m1r = mn1;

            float rs0 = 0.0f, rs1 = 0.0f;
#pragma unroll
            for (int nt = 0; nt < 8; nt++) {
                s[nt][0] = ex2(s[nt][0] - mn0);
                s[nt][1] = ex2(s[nt][1] - mn0);
                s[nt][2] = ex2(s[nt][2] - mn1);
                s[nt][3] = ex2(s[nt][3] - mn1);
                rs0 += s[nt][0] + s[nt][1];
                rs1 += s[nt][2] + s[nt][3];
            }
            rs0 += __shfl_xor_sync(0xffffffffu, rs0, 1);
            rs0 += __shfl_xor_sync(0xffffffffu, rs0, 2);
            rs1 += __shfl_xor_sync(0xffffffffu, rs1, 1);
            rs1 += __shfl_xor_sync(0xffffffffu, rs1, 2);

            l0r = l0r * c0 + rs0;
            l1r = l1r * c1 + rs1;
#pragma unroll
            for (int nt = 0; nt < 8; nt++) {
                o[nt][0] *= c0; o[nt][1] *= c0;
                o[nt][2] *= c1; o[nt][3] *= c1;
            }
        }

#pragma unroll
        for (int j = 0; j < 4; j++) {
            uint32_t ah[4];
            ah[0] = pack_h2(s[2*j][0],   s[2*j][1]);
            ah[1] = pack_h2(s[2*j][2],   s[2*j][3]);
            ah[2] = pack_h2(s[2*j+1][0], s[2*j+1][1]);
            ah[3] = pack_h2(s[2*j+1][2], s[2*j+1][3]);
#pragma unroll
            for (int nt = 0; nt < 8; nt++) {
                int wb = (j * 8 + tig) * VP + nt * 8 + gid;
                mma_f16(o[nt], ah, Vph[wb], Vph[wb + 4 * VP]);
            }
        }
        __syncthreads();
        if (i < 14) issue_kv((i + 2) * 64, buf_off);
    };

    for (int ii = 0; ii < 8; ii++) {
        proc(2 * ii,     sm_kv,         0);
        proc(2 * ii + 1, sm_kv + STG_W, STG_W * 4u);
    }

    // ---- normalize + write hi/lo fp16 split (token-major) ----
    {
        float i0 = 1.0f / l0r, i1 = 1.0f / l1r;
        const int r0g = q0 + wm + gid;
        size_t base0 = (size_t)(r0g * B_DIM + b) * DMODEL + h * HEAD_DIM;
        size_t base1 = base0 + (size_t)8 * B_DIM * DMODEL;
        uint32_t* ahw = (uint32_t*)g_ah;
        uint32_t* alw = (uint32_t*)g_al;
#pragma unroll
        for (int nt = 0; nt < 8; nt++) {
            int c = nt * 8 + 2 * tig;
            uint32_t hi, lo;
            split_h2(o[nt][0] * i0, o[nt][1] * i0, hi, lo);
            ahw[(base0 + c) >> 1] = hi;
            alw[(base0 + c) >> 1] = lo;
            split_h2(o[nt][2] * i1, o[nt][3] * i1, hi, lo);
            ahw[(base1 + c) >> 1] = hi;
            alw[(base1 + c) >> 1] = lo;
        }
    }
}

// ---------------------------------------------------------------------------

extern "C" void kernel_launch(void* const* d_in, const int* in_sizes, int n_in,
                              void* d_out, int out_size)
{
    const float* src   = (const float*)d_in[0];
    const float* rbias = (const float*)d_in[1];
    const float* Wq    = (const float*)d_in[2];
    const float* bq    = (const float*)d_in[3];
    const float* Wk    = (const float*)d_in[4];
    const float* bk    = (const float*)d_in[5];
    const float* Wv    = (const float*)d_in[6];
    const float* bv    = (const float*)d_in[7];
    const float* Wo    = (const float*)d_in[8];
    const float* bo    = (const float*)d_in[9];
    float* out = (float*)d_out;

    float* grb;
    cudaGetSymbolAddress((void**)&grb, g_rb2);

    const int gsm = 2 * STAGE_W * 4;   // 61440 B
    cudaFuncSetAttribute(gemm_qkv, cudaFuncAttributeMaxDynamicSharedMemorySize, gsm);
    cudaFuncSetAttribute(gemm_out, cudaFuncAttributeMaxDynamicSharedMemorySize, gsm);

    // 1) prep: split X to fp16 hi/lo, round W's to fp16, scale rbias
    prep_all<<<(NX4 + 4 * NW4 + NR4 + 255) / 256, 256>>>(
        (const float4*)src, (const float4*)Wq, (const float4*)Wk,
        (const float4*)Wv, (const float4*)Wo, (const float4*)rbias,
        (float4*)grb);

    // 2) fused QKV projection (fp16 2-term, attention-native outputs)
    gemm_qkv<<<dim3(128, 4, 3), 256, gsm>>>(bq, bk, bv);

    // 3) attention
    attn_mma<<<dim3(A_DIM / 128, B_DIM * NHEAD), 256>>>(grb);

    // 4) output projection (fp16 2-term)
    gemm_out<<<dim3(128, 4, 1), 256, gsm>>>(bo, out);
}